// round 4
// baseline (speedup 1.0000x reference)
#include <cuda_runtime.h>
#include <cstdint>

#define B_ 8
#define N_ 16384
#define M_ 1024
#define C_ 64
#define NS_ 32
#define COUT_ 67
#define R2_ 0.04f
#define TILE_PTS 1024

// Scratch: transposed features (B, N, C) = 32 MB, and ball-query indices = 1 MB.
__device__ float g_ft[(size_t)B_ * N_ * C_];
__device__ int   g_idx[(size_t)B_ * M_ * NS_];

// ---------------------------------------------------------------------------
// Kernel 1: transpose features (B, C, N) -> (B, N, C), float4 both directions.
// Tile: 32 n x 32 c. Block (8, 32): thread (tx, ty) loads float4 along N,
// stores float4 along C. Coalesced 128B segments both ways.
// ---------------------------------------------------------------------------
__global__ void transpose_kernel(const float* __restrict__ f) {
    __shared__ float tile[32][33];       // tile[c][n]
    const int b  = blockIdx.z;
    const int n0 = blockIdx.x * 32;
    const int c0 = blockIdx.y * 32;
    const int tx = threadIdx.x;          // 0..7
    const int ty = threadIdx.y;          // 0..31

    const float* src = f + (size_t)b * C_ * N_;
    float*       dst = g_ft + (size_t)b * N_ * C_;

    // Load: c = c0+ty, n = n0 + tx*4 .. +3 (contiguous in N)
    const float4 v = *(const float4*)(src + (size_t)(c0 + ty) * N_ + n0 + tx * 4);
    tile[ty][tx * 4 + 0] = v.x;
    tile[ty][tx * 4 + 1] = v.y;
    tile[ty][tx * 4 + 2] = v.z;
    tile[ty][tx * 4 + 3] = v.w;
    __syncthreads();

    // Store: n = n0+ty, c = c0 + tx*4 .. +3 (contiguous in C)
    float4 o;
    o.x = tile[tx * 4 + 0][ty];
    o.y = tile[tx * 4 + 1][ty];
    o.z = tile[tx * 4 + 2][ty];
    o.w = tile[tx * 4 + 3][ty];
    *(float4*)(dst + (size_t)(n0 + ty) * C_ + c0 + tx * 4) = o;
}

// ---------------------------------------------------------------------------
// Kernel 2: ball query, strip-parallel cooperative version.
// Block = 8 warps handling 8 queries (same batch). Per 1024-pt smem tile,
// warp w scans strip [w*128, (w+1)*128) for EVERY unfinished query (strips
// preserve ascending index order). Then warp j merges query j's 8 per-strip
// ordered hit lists prefix-wise into its accumulated result. Per-query done
// flags shrink the straggler tail ~8x vs one-warp-per-query.
// ---------------------------------------------------------------------------
__global__ void ballquery_kernel(const float* __restrict__ xyz,
                                 const float* __restrict__ new_xyz) {
    __shared__ float4 spts[TILE_PTS];       // 16 KB, {x,y,z,0}
    __shared__ int    shidx[8][8][NS_];     // [query][strip][slot], 8 KB
    __shared__ int    scnt[8][8];           // per-tile strip hit counts
    __shared__ int    sres[8][NS_];         // accumulated first-32 indices
    __shared__ int    scur[8];              // accumulated count (<=32)
    __shared__ int    sdone[8];
    __shared__ int    sdone_cnt;
    __shared__ float  sqx[8], sqy[8], sqz[8];

    const int tid  = threadIdx.x;
    const int w    = tid >> 5;
    const int lane = tid & 31;
    const int qbase = blockIdx.x * 8;       // 8 queries, all same batch
    const int b     = qbase >> 10;
    const float* xb = xyz + (size_t)b * N_ * 3;

    if (tid < 8) {
        scur[tid]  = 0;
        sdone[tid] = 0;
        const float* qp = new_xyz + (size_t)(qbase + tid) * 3;
        sqx[tid] = qp[0]; sqy[tid] = qp[1]; sqz[tid] = qp[2];
    }
    if (tid == 0) sdone_cnt = 0;
    __syncthreads();

    const unsigned lanemask_lt = (1u << lane) - 1u;

    for (int t0 = 0; t0 < N_; t0 += TILE_PTS) {
        // Cooperative tile load: 4 points per thread via 3 float4 loads.
        {
            const float4* src = (const float4*)(xb + (size_t)t0 * 3);
            const float4 a = src[tid * 3 + 0];
            const float4 c = src[tid * 3 + 1];
            const float4 d = src[tid * 3 + 2];
            spts[tid * 4 + 0] = make_float4(a.x, a.y, a.z, 0.f);
            spts[tid * 4 + 1] = make_float4(a.w, c.x, c.y, 0.f);
            spts[tid * 4 + 2] = make_float4(c.z, c.w, d.x, 0.f);
            spts[tid * 4 + 3] = make_float4(d.y, d.z, d.w, 0.f);
        }
        __syncthreads();

        // Scan: warp w handles strip w for every unfinished query.
        const int base = w * 128;
#pragma unroll 1
        for (int j = 0; j < 8; j++) {
            if (sdone[j]) continue;
            const float qx = sqx[j], qy = sqy[j], qz = sqz[j];
            int cnt = 0;
#pragma unroll
            for (int g = 0; g < 4; g++) {
                const int nl = base + g * 32 + lane;
                const float4 p = spts[nl];
                const float dx = p.x - qx, dy = p.y - qy, dz = p.z - qz;
                const bool hit = dx * dx + dy * dy + dz * dz < R2_;
                const unsigned msk = __ballot_sync(0xffffffffu, hit);
                const int pos = cnt + __popc(msk & lanemask_lt);
                if (hit && pos < NS_) shidx[j][w][pos] = t0 + nl;
                cnt += __popc(msk);
            }
            if (lane == 0) scnt[j][w] = cnt;
        }
        __syncthreads();

        // Merge: warp j folds query j's strip lists (prefix order).
        {
            const int j = w;
            if (!sdone[j]) {
                int cur = scur[j];
#pragma unroll
                for (int s = 0; s < 8; s++) {
                    const int c    = scnt[j][s];
                    const int take = min(c, NS_ - cur);
                    if (lane < take) sres[j][cur + lane] = shidx[j][s][lane];
                    cur += take;
                }
                if (lane == 0) {
                    scur[j] = cur;
                    if (cur >= NS_) { sdone[j] = 1; atomicAdd(&sdone_cnt, 1); }
                }
            }
        }
        __syncthreads();
        if (sdone_cnt == 8) break;
    }

    // Epilogue: warp j writes query j. cur==0 -> all-invalid -> clamp to N-1.
    {
        const int j   = w;
        const int cur = scur[j];
        int v;
        if (cur == 0) v = N_ - 1;
        else          v = (lane < cur) ? sres[j][lane] : sres[j][0];
        g_idx[(size_t)(qbase + j) * NS_ + lane] = v;
    }
}

// ---------------------------------------------------------------------------
// Kernel 3: grouping. One block per (b, m). Gather 64 contiguous channels per
// index from the transposed features (256B coalesced per sample), plus the
// xyz diff; stage in a 67x33 smem tile; write output fully coalesced.
// ---------------------------------------------------------------------------
__global__ void group_kernel(const float* __restrict__ xyz,
                             const float* __restrict__ new_xyz,
                             float* __restrict__ out) {
    __shared__ int   sidx[NS_];
    __shared__ float tile[COUT_][33];

    const int bm = blockIdx.x;
    const int b  = bm >> 10;
    const int m  = bm & (M_ - 1);
    const int t  = threadIdx.x;          // 256 threads
    const int w  = t >> 5;
    const int lane = t & 31;

    if (t < NS_) sidx[t] = g_idx[(size_t)bm * NS_ + t];
    __syncthreads();

    const float* ftb = g_ft + (size_t)b * N_ * C_;
    const float* qp  = new_xyz + ((size_t)b * M_ + m) * 3;

#pragma unroll
    for (int k = 0; k < 4; k++) {
        const int s = w + k * 8;         // 8 warps cover 32 samples
        const int n = sidx[s];
        const float* col = ftb + (size_t)n * C_;
        tile[3 + lane][s]      = col[lane];
        tile[3 + 32 + lane][s] = col[lane + 32];
        if (lane < 3)
            tile[lane][s] = xyz[((size_t)b * N_ + n) * 3 + lane] - qp[lane];
    }
    __syncthreads();

    float* ob = out + ((size_t)b * COUT_ * M_ + m) * NS_;
    for (int e = t; e < COUT_ * NS_; e += 256) {
        const int c = e >> 5;
        const int s = e & 31;
        ob[(size_t)c * M_ * NS_ + s] = tile[c][s];
    }
}

// ---------------------------------------------------------------------------
extern "C" void kernel_launch(void* const* d_in, const int* in_sizes, int n_in,
                              void* d_out, int out_size) {
    const float* xyz = nullptr;
    const float* new_xyz = nullptr;
    const float* feats = nullptr;
    for (int i = 0; i < n_in; i++) {
        if (in_sizes[i] == B_ * N_ * 3)      xyz     = (const float*)d_in[i];
        else if (in_sizes[i] == B_ * M_ * 3) new_xyz = (const float*)d_in[i];
        else if (in_sizes[i] == B_ * C_ * N_) feats  = (const float*)d_in[i];
    }
    float* out = (float*)d_out;

    ballquery_kernel<<<(B_ * M_) / 8, 256>>>(xyz, new_xyz);

    dim3 tgrid(N_ / 32, C_ / 32, B_);
    transpose_kernel<<<tgrid, dim3(8, 32)>>>(feats);

    group_kernel<<<B_ * M_, 256>>>(xyz, new_xyz, out);
}